// round 15
// baseline (speedup 1.0000x reference)
#include <cuda_runtime.h>
#include <cuda_fp16.h>
#include <cstdint>

#define DD    64
#define HATTN 256
#define NMAX  2048

// ---------------- device-global scratch (no allocs allowed) ----------------
__device__ float  g_Wqa[DD * HATTN];
__device__ float  g_Wka[DD * HATTN];
__device__ float  g_W12[DD * HATTN];      // (pW2@aW1)[h][c]
__device__ float  g_bqa[HATTN];
__device__ float  g_qa [NMAX * HATTN];    // fp32
__device__ float  g_part[2 * NMAX * 128]; // per-(i,half): [0:64) S, [64:128) A
// fragment-ordered fp16 data images (coalesced LDG per fragment):
__device__ uint4  g_dff[(NMAX / 16) * 4 * 32];      // d = pos@pW1: [rb][kk][lane]
__device__ uint2  g_kaf[(NMAX / 16) * 8 * 4 * 32];  // ka: [rb][chk][nt][lane]
__device__ uint2  g_vsf[(NMAX / 16) * 8 * 32];      // vs=x@Wv: [rb][nt2][lane]
// PAIRED fp16 B-fragment weight images: uint4 = two adjacent-n fragments
__device__ uint4  g_W1q [2048];           // W12 : [kk*16 + chk*2 + p][lane]
__device__ uint4  g_aW2q[2048];           // aW2 : [kkg*4 + pp][lane]
__device__ uint4  g_pW2q[512];            // pW2 : [kk*4 + pp][lane]

__device__ __forceinline__ unsigned fp2h2(float a, float b) {
    __half2 h = __floats2half2_rn(a, b);
    return *reinterpret_cast<unsigned*>(&h);
}
__device__ __forceinline__ void mma16(float* c, const unsigned* a, unsigned bx, unsigned by) {
    asm volatile("mma.sync.aligned.m16n8k16.row.col.f32.f16.f16.f32 "
                 "{%0,%1,%2,%3}, {%4,%5,%6,%7}, {%8,%9}, {%0,%1,%2,%3};"
                 : "+f"(c[0]), "+f"(c[1]), "+f"(c[2]), "+f"(c[3])
                 : "r"(a[0]), "r"(a[1]), "r"(a[2]), "r"(a[3]), "r"(bx), "r"(by));
}
__device__ __forceinline__ void mma16h(unsigned* d, const unsigned* a, unsigned bx, unsigned by) {
    asm volatile("mma.sync.aligned.m16n8k16.row.col.f16.f16.f16.f16 "
                 "{%0,%1}, {%2,%3,%4,%5}, {%6,%7}, {%0,%1};"
                 : "+r"(d[0]), "+r"(d[1])
                 : "r"(a[0]), "r"(a[1]), "r"(a[2]), "r"(a[3]), "r"(bx), "r"(by));
}

// ---------------------------------------------------------------------------
// prep1: weight folds W12 = pW2@aW1, Wqa = Wq@aW1, Wka = Wk@aW1, bqa.
// ---------------------------------------------------------------------------
__global__ void prep1(const float* __restrict__ Wq, const float* __restrict__ Wk,
                      const float* __restrict__ pW2, const float* __restrict__ aW1,
                      const float* __restrict__ ab1, const float* __restrict__ pb2)
{
    __shared__ float srow[3][DD];
    const int r = blockIdx.x, c = threadIdx.x;
    if (c < 64)       srow[0][c]       = Wq [r * DD + c];
    else if (c < 128) srow[1][c - 64]  = Wk [r * DD + (c - 64)];
    else if (c < 192) srow[2][c - 128] = pW2[r * DD + (c - 128)];
    __syncthreads();
    float wq = 0.f, wk = 0.f, w12 = 0.f;
    #pragma unroll 8
    for (int t = 0; t < DD; ++t) {
        float a = aW1[t * HATTN + c];
        wq  = fmaf(srow[0][t], a, wq);
        wk  = fmaf(srow[1][t], a, wk);
        w12 = fmaf(srow[2][t], a, w12);
    }
    g_Wqa[r * HATTN + c] = wq;
    g_Wka[r * HATTN + c] = wk;
    g_W12[r * HATTN + c] = w12;
    if (r == 0) {
        float b = ab1[c];
        for (int t = 0; t < DD; ++t) b = fmaf(pb2[t], aW1[t * HATTN + c], b);
        g_bqa[c] = b;
    }
}

// ---------------------------------------------------------------------------
// prepF: pack W12 / aW2 / pW2 into PAIRED fp16 B-fragment uint4 images.
// ---------------------------------------------------------------------------
__global__ void prepF(const float* __restrict__ aW2, const float* __restrict__ pW2)
{
    const int e = blockIdx.x * 256 + threadIdx.x;
    const int lane = e & 31, gg = lane >> 2, tg = lane & 3;
    if (e < 4096) {                                      // W12, K=64, N=256
        const int kk = e >> 10, nt = (e >> 5) & 31;
        const int k0 = 16 * kk + 2 * tg, n0 = 8 * nt + gg;
        unsigned vx = fp2h2(g_W12[(k0    ) * HATTN + n0], g_W12[(k0 + 1) * HATTN + n0]);
        unsigned vy = fp2h2(g_W12[(k0 + 8) * HATTN + n0], g_W12[(k0 + 9) * HATTN + n0]);
        // chunk = nt>>2, within-chunk pos = nt&3 -> pair p = (nt&3)>>1, comp = nt&1
        const int chk = nt >> 2, p = (nt >> 1) & 1, comp = nt & 1;
        unsigned* W = (unsigned*)g_W1q;
        const int base = (((kk * 16) + chk * 2 + p) * 32 + lane) * 4 + comp * 2;
        W[base] = vx;  W[base + 1] = vy;
    } else if (e < 8192) {                               // aW2, K=256, N=64
        const int l = e - 4096;
        const int kk = l >> 8, nt = (l >> 5) & 7;        // kk = chk*2+kk2 (0..15)
        const int k0 = 16 * kk + 2 * tg, n0 = 8 * nt + gg;
        unsigned vx = fp2h2(aW2[(k0    ) * DD + n0], aW2[(k0 + 1) * DD + n0]);
        unsigned vy = fp2h2(aW2[(k0 + 8) * DD + n0], aW2[(k0 + 9) * DD + n0]);
        unsigned* W = (unsigned*)g_aW2q;
        const int base = ((kk * 4 + (nt >> 1)) * 32 + lane) * 4 + (nt & 1) * 2;
        W[base] = vx;  W[base + 1] = vy;
    } else if (e < 9216) {                               // pW2, K=64, N=64
        const int l = e - 8192;
        const int kk = l >> 8, nt = (l >> 5) & 7;
        const int k0 = 16 * kk + 2 * tg, n0 = 8 * nt + gg;
        unsigned vx = fp2h2(pW2[(k0    ) * DD + n0], pW2[(k0 + 1) * DD + n0]);
        unsigned vy = fp2h2(pW2[(k0 + 8) * DD + n0], pW2[(k0 + 9) * DD + n0]);
        unsigned* W = (unsigned*)g_pW2q;
        const int base = ((kk * 4 + (nt >> 1)) * 32 + lane) * 4 + (nt & 1) * 2;
        W[base] = vx;  W[base + 1] = vy;
    }
}

// ---------------------------------------------------------------------------
// prep2: 8 points per block (weights read ONCE per block, not per point).
// grid = N/8, block = 256.
// ---------------------------------------------------------------------------
__global__ void prep2(const float* __restrict__ x, const float* __restrict__ pos,
                      const float* __restrict__ Wv, const float* __restrict__ pW1,
                      int N)
{
    __shared__ float sx[8][DD];
    const int n0 = blockIdx.x * 8, c = threadIdx.x;
    for (int idx = c; idx < 8 * DD; idx += 256)
        sx[idx >> 6][idx & 63] = x[(n0 + (idx >> 6)) * DD + (idx & 63)];
    __syncthreads();

    float aq[8], ak[8];
    #pragma unroll
    for (int p = 0; p < 8; ++p) { aq[p] = g_bqa[c]; ak[p] = 0.f; }
    #pragma unroll 4
    for (int t = 0; t < DD; ++t) {
        const float wq = g_Wqa[t * HATTN + c];
        const float wk = g_Wka[t * HATTN + c];
        #pragma unroll
        for (int p = 0; p < 8; ++p) {
            const float xv = sx[p][t];
            aq[p] = fmaf(xv, wq, aq[p]);
            ak[p] = fmaf(xv, wk, ak[p]);
        }
    }
    #pragma unroll
    for (int p = 0; p < 8; ++p) {
        const int n = n0 + p;
        g_qa[n * HATTN + c] = aq[p];
        const int rb = n >> 4, rr = n & 15, gg = rr & 7, hi = rr >> 3;
        const int chk = c >> 5, nt = (c >> 3) & 3, tg = (c & 7) >> 1, lo = c & 1;
        const int ent = ((rb * 8 + chk) * 4 + nt) * 32 + (gg * 4 + tg);
        reinterpret_cast<__half*>(g_kaf)[ent * 4 + hi * 2 + lo] = __float2half(ak[p]);
    }
    if (c < DD) {
        float av[8];
        #pragma unroll
        for (int p = 0; p < 8; ++p) av[p] = 0.f;
        #pragma unroll 4
        for (int t = 0; t < DD; ++t) {
            const float wv = Wv[t * DD + c];
            #pragma unroll
            for (int p = 0; p < 8; ++p) av[p] = fmaf(sx[p][t], wv, av[p]);
        }
        const float w1x = pW1[c], w1y = pW1[DD + c];
        #pragma unroll
        for (int p = 0; p < 8; ++p) {
            const int n = n0 + p;
            const int rb = n >> 4, rr = n & 15, gg = rr & 7, hi = rr >> 3;
            const int nt2 = c >> 3, tg = (c & 7) >> 1, lo = c & 1;
            const int ent = (rb * 8 + nt2) * 32 + (gg * 4 + tg);
            reinterpret_cast<__half*>(g_vsf)[ent * 4 + hi * 2 + lo] = __float2half(av[p]);
            const float dval = fmaf(pos[2 * n], w1x, pos[2 * n + 1] * w1y);
            const int w16 = c & 15, kk = c >> 4, tg2 = (w16 & 7) >> 1, lo2 = c & 1;
            const int comp = ((w16 >= 8) ? 2 : 0) + ((rr >= 8) ? 1 : 0);
            const int ent2 = (rb * 4 + kk) * 32 + (gg * 4 + tg2);
            reinterpret_cast<__half*>(g_dff)[ent2 * 8 + comp * 2 + lo2] = __float2half(dval);
        }
    }
}

// ---------------------------------------------------------------------------
// main: grid = 2N; round-14 core with paired uint4 B-fragment loads (LDS.128).
// ---------------------------------------------------------------------------
#define OFF_W1Q  0
#define OFF_AW2Q 32768
#define OFF_PW2Q 65536
#define OFF_QAH  73728
#define OFF_CIH  74240
#define OFF_REDS 74496
#define OFF_REDA 76544
#define SMEM_SZ  78592

__global__ void __launch_bounds__(256, 2)
pt_main(const float* __restrict__ pos, const float* __restrict__ pW1,
        const float* __restrict__ pb1, int N)
{
    extern __shared__ char smem[];
    uint4*   sW1q  = (uint4*)(smem + OFF_W1Q);
    uint4*   sAW2q = (uint4*)(smem + OFF_AW2Q);
    uint4*   sPW2q = (uint4*)(smem + OFF_PW2Q);
    __half2* sQah  = (__half2*)(smem + OFF_QAH);
    __half2* sCih  = (__half2*)(smem + OFF_CIH);
    float*   sRedS = (float*)(smem + OFF_REDS);
    float*   sRedA = (float*)(smem + OFF_REDA);

    const int tid  = threadIdx.x;
    const int i    = blockIdx.x >> 1;
    const int half = blockIdx.x & 1;
    const int w    = tid >> 5, lane = tid & 31;
    const int g    = lane >> 2, tig = lane & 3;

    {   // stage weight fragment images
        for (int k = tid; k < 2048; k += 256) { sW1q[k] = g_W1q[k]; sAW2q[k] = g_aW2q[k]; }
        for (int k = tid; k < 512;  k += 256) sPW2q[k] = g_pW2q[k];
    }
    if (tid < 128) {
        float2 q = *(const float2*)&g_qa[i * HATTN + 2 * tid];
        sQah[tid] = __floats2half2_rn(q.x, q.y);
    }
    const float posIx = pos[2 * i], posIy = pos[2 * i + 1];
    if (tid < 32) {   // ci (pos-MLP hidden pre-activation for query i), half2 pairs
        const int kk = tid >> 3, r = tid & 7, tg = r & 3, hb = r >> 2;
        const int c0 = 16 * kk + 2 * tg + 8 * hb;
        float f0 = fmaf(posIx, pW1[c0],     fmaf(posIy, pW1[DD + c0],     pb1[c0]));
        float f1 = fmaf(posIx, pW1[c0 + 1], fmaf(posIy, pW1[DD + c0 + 1], pb1[c0 + 1]));
        sCih[kk * 8 + hb * 4 + tg] = __floats2half2_rn(f0, f1);
    }
    sRedS[tid] = 0.f; sRedS[tid + 256] = 0.f;
    sRedA[tid] = 0.f; sRedA[tid + 256] = 0.f;
    __syncthreads();

    const __half2 hzero = __float2half2_rn(0.f);
    const int ntile = N >> 7;
    const int jt0 = half * (ntile >> 1);
    const int jt1 = half ? ntile : (ntile >> 1);

    // d-fragment prefetch for the first tile
    uint4 dnx[4];
    {
        const int rb = jt0 * 8 + w;
        #pragma unroll
        for (int kk = 0; kk < 4; ++kk)
            dnx[kk] = __ldg(&g_dff[(rb * 4 + kk) * 32 + lane]);
    }

    for (int jt = jt0; jt < jt1; ++jt) {
        const int rb = jt * 8 + w;
        const uint2* kaRow = &g_kaf[rb * 8 * 4 * 32];
        const uint2* vsRow = &g_vsf[rb * 8 * 32];

        // ---- A fragments: U = relu(ci - d), pure fp16, from prefetched image ----
        unsigned Af[4][4];
        #pragma unroll
        for (int kk = 0; kk < 4; ++kk) {
            const __half2 cl = sCih[kk * 8 + tig];
            const __half2 ch = sCih[kk * 8 + 4 + tig];
            uint4 dv = dnx[kk];
            __half2 u0 = __hmax2(__hsub2(cl, *reinterpret_cast<__half2*>(&dv.x)), hzero);
            __half2 u1 = __hmax2(__hsub2(cl, *reinterpret_cast<__half2*>(&dv.y)), hzero);
            __half2 u2 = __hmax2(__hsub2(ch, *reinterpret_cast<__half2*>(&dv.z)), hzero);
            __half2 u3 = __hmax2(__hsub2(ch, *reinterpret_cast<__half2*>(&dv.w)), hzero);
            Af[kk][0] = *reinterpret_cast<unsigned*>(&u0);
            Af[kk][1] = *reinterpret_cast<unsigned*>(&u1);
            Af[kk][2] = *reinterpret_cast<unsigned*>(&u2);
            Af[kk][3] = *reinterpret_cast<unsigned*>(&u3);
        }

        float sc[8][4];
        #pragma unroll
        for (int a = 0; a < 8; ++a)
            { sc[a][0]=0.f; sc[a][1]=0.f; sc[a][2]=0.f; sc[a][3]=0.f; }

        // ka double-buffer: chunk 0 preloaded; chunk c+1 issued at top of c
        uint2 kac[4];
        #pragma unroll
        for (int nt = 0; nt < 4; ++nt)
            kac[nt] = __ldg(&kaRow[nt * 32 + lane]);

        #pragma unroll 1
        for (int chk = 0; chk < 8; ++chk) {              // 32 attn channels / chunk
            uint2 kan[4];
            const int cn = (chk + 1) & 7;                // wrap: harmless reload at tail
            #pragma unroll
            for (int nt = 0; nt < 4; ++nt)
                kan[nt] = __ldg(&kaRow[(cn * 4 + nt) * 32 + lane]);

            // GEMM1: P = U @ W12 (K=64), fp16 C; paired LDS.128 B loads
            unsigned pa[4][2];
            #pragma unroll
            for (int a = 0; a < 4; ++a) { pa[a][0] = 0u; pa[a][1] = 0u; }
            #pragma unroll
            for (int kk = 0; kk < 4; ++kk) {
                uint4 B01 = sW1q[((kk * 16) + chk * 2 + 0) * 32 + lane];
                uint4 B23 = sW1q[((kk * 16) + chk * 2 + 1) * 32 + lane];
                mma16h(pa[0], Af[kk], B01.x, B01.y);
                mma16h(pa[1], Af[kk], B01.z, B01.w);
                mma16h(pa[2], Af[kk], B23.x, B23.y);
                mma16h(pa[3], Af[kk], B23.z, B23.w);
            }
            // epilogue: v = relu(pa + qa - ka); fp16 D layout == GEMM2 A layout
            unsigned a2[2][4];
            #pragma unroll
            for (int nt = 0; nt < 4; ++nt) {
                const __half2 qa2 = sQah[chk * 16 + nt * 4 + tig];
                __half2 qk0 = __hsub2(qa2, *reinterpret_cast<__half2*>(&kac[nt].x));
                __half2 qk1 = __hsub2(qa2, *reinterpret_cast<__half2*>(&kac[nt].y));
                __half2 r0  = __hmax2(__hadd2(*reinterpret_cast<__half2*>(&pa[nt][0]), qk0), hzero);
                __half2 r1  = __hmax2(__hadd2(*reinterpret_cast<__half2*>(&pa[nt][1]), qk1), hzero);
                const int kk2 = nt >> 1, sl = (nt & 1) << 1;
                a2[kk2][sl]     = *reinterpret_cast<unsigned*>(&r0);
                a2[kk2][sl + 1] = *reinterpret_cast<unsigned*>(&r1);
            }
            // GEMM2 partial: sim += P' @ aW2 (K=32 this chunk), fp32 C; LDS.128
            #pragma unroll
            for (int kk2 = 0; kk2 < 2; ++kk2)
                #pragma unroll
                for (int pp = 0; pp < 4; ++pp) {
                    uint4 Bq = sAW2q[(((chk * 2 + kk2) * 4) + pp) * 32 + lane];
                    mma16(sc[2 * pp],     a2[kk2], Bq.x, Bq.y);
                    mma16(sc[2 * pp + 1], a2[kk2], Bq.z, Bq.w);
                }
            #pragma unroll
            for (int nt = 0; nt < 4; ++nt) kac[nt] = kan[nt];
        }

        // prefetch d fragments for next tile (pa/a2 dead here -> regs free)
        {
            const int jn  = (jt + 1 < jt1) ? jt + 1 : jt0;
            const int rbn = jn * 8 + w;
            #pragma unroll
            for (int kk = 0; kk < 4; ++kk)
                dnx[kk] = __ldg(&g_dff[(rbn * 4 + kk) * 32 + lane]);
        }

        // vs fragments (coalesced LDG.64; overlap GEMM3)
        uint2 vsfr[8];
        #pragma unroll
        for (int nt2 = 0; nt2 < 8; ++nt2)
            vsfr[nt2] = __ldg(&vsRow[nt2 * 32 + lane]);

        // GEMM3: rpe = U @ pW2 (K=64), fp16 C; paired LDS.128 B loads
        unsigned ra[8][2];
        #pragma unroll
        for (int a = 0; a < 8; ++a) { ra[a][0] = 0u; ra[a][1] = 0u; }
        #pragma unroll
        for (int kk = 0; kk < 4; ++kk)
            #pragma unroll
            for (int pp = 0; pp < 4; ++pp) {
                uint4 Bq = sPW2q[(kk * 4 + pp) * 32 + lane];
                mma16h(ra[2 * pp],     Af[kk], Bq.x, Bq.y);
                mma16h(ra[2 * pp + 1], Af[kk], Bq.z, Bq.w);
            }

        // exp + weighted accumulation, then per-tile reduce over rows
        float Sr[16], Ar[16];
        #pragma unroll
        for (int nt2 = 0; nt2 < 8; ++nt2) {
            __half2 vv0 = __hadd2(*reinterpret_cast<__half2*>(&vsfr[nt2].x),
                                  *reinterpret_cast<__half2*>(&ra[nt2][0]));
            __half2 vv1 = __hadd2(*reinterpret_cast<__half2*>(&vsfr[nt2].y),
                                  *reinterpret_cast<__half2*>(&ra[nt2][1]));
            float2 vl = __half22float2(vv0);
            float2 vh = __half22float2(vv1);
            float e0 = __expf(sc[nt2][0]);
            float e1 = __expf(sc[nt2][1]);
            float e2 = __expf(sc[nt2][2]);
            float e3 = __expf(sc[nt2][3]);
            Sr[nt2 * 2 + 0] = e0 + e2;
            Sr[nt2 * 2 + 1] = e1 + e3;
            Ar[nt2 * 2 + 0] = e0 * vl.x + e2 * vh.x;
            Ar[nt2 * 2 + 1] = e1 * vl.y + e3 * vh.y;
        }
        #pragma unroll
        for (int q = 0; q < 16; ++q) {
            float s = Sr[q], a = Ar[q];
            s += __shfl_xor_sync(0xffffffffu, s, 4);
            a += __shfl_xor_sync(0xffffffffu, a, 4);
            s += __shfl_xor_sync(0xffffffffu, s, 8);
            a += __shfl_xor_sync(0xffffffffu, a, 8);
            s += __shfl_xor_sync(0xffffffffu, s, 16);
            a += __shfl_xor_sync(0xffffffffu, a, 16);
            Sr[q] = s; Ar[q] = a;
        }
        if (lane < 4) {
            #pragma unroll
            for (int nt2 = 0; nt2 < 8; ++nt2) {
                const int d0 = w * DD + nt2 * 8 + 2 * lane;
                sRedS[d0]     += Sr[nt2 * 2 + 0];
                sRedS[d0 + 1] += Sr[nt2 * 2 + 1];
                sRedA[d0]     += Ar[nt2 * 2 + 0];
                sRedA[d0 + 1] += Ar[nt2 * 2 + 1];
            }
        }
    }

    __syncthreads();
    if (tid < DD) {
        float s = 0.f, a = 0.f;
        #pragma unroll
        for (int q = 0; q < 8; ++q) { s += sRedS[q * DD + tid]; a += sRedA[q * DD + tid]; }
        g_part[blockIdx.x * 128 + tid]      = s;
        g_part[blockIdx.x * 128 + 64 + tid] = a;
    }
}

// ---------------------------------------------------------------------------
// combine: out[i][d] = (A0+A1)/(S0+S1) + pb2[d]  (fixed order -> deterministic)
// ---------------------------------------------------------------------------
__global__ void combine(const float* __restrict__ pb2, float* __restrict__ out, int N)
{
    const int i = blockIdx.x, t = threadIdx.x;
    float s = g_part[(2 * i) * 128 + t]      + g_part[(2 * i + 1) * 128 + t];
    float a = g_part[(2 * i) * 128 + 64 + t] + g_part[(2 * i + 1) * 128 + 64 + t];
    out[i * DD + t] = a / s + pb2[t];
}

// ---------------------------------------------------------------------------
extern "C" void kernel_launch(void* const* d_in, const int* in_sizes, int n_in,
                              void* d_out, int out_size)
{
    const float* x   = (const float*)d_in[0];
    const float* pos = (const float*)d_in[1];
    const float* Wq  = (const float*)d_in[2];
    const float* Wk  = (const float*)d_in[3];
    const float* Wv  = (const float*)d_in[4];
    const float* pW1 = (const float*)d_in[5];
    const float* pb1 = (const float*)d_in[6];
    const float* pW2 = (const float*)d_in[7];
    const float* pb2 = (const float*)d_in[8];
    const float* aW1 = (const float*)d_in[9];
    const float* ab1 = (const float*)d_in[10];
    const float* aW2 = (const float*)d_in[11];
    // d_in[12] = ab2: constant over j -> softmax-invariant -> unused.

    const int N = in_sizes[0] / DD;   // B = 1
    float* out  = (float*)d_out;

    prep1<<<DD, 256>>>(Wq, Wk, pW2, aW1, ab1, pb2);
    prepF<<<36, 256>>>(aW2, pW2);
    prep2<<<N / 8, 256>>>(x, pos, Wv, pW1, N);

    cudaFuncSetAttribute((const void*)pt_main,
                         cudaFuncAttributeMaxDynamicSharedMemorySize, SMEM_SZ);
    pt_main<<<2 * N, 256, SMEM_SZ>>>(pos, pW1, pb1, N);
    combine<<<N, DD>>>(pb2, out, N);
}